// round 15
// baseline (speedup 1.0000x reference)
#include <cuda_runtime.h>
#include <cstdint>

#define BB 4096
#define NN 8192
#define DD 512
#define RR 4
#define NBLK (NN / 4)   // 2048 blocks, 4 warps = 4 rows per block

__device__ float g_partial[NBLK];
__device__ unsigned int g_ticket;   // zero-init at load; reset by block 0 each run

__device__ __forceinline__ const float* row_ptr(const float* zi, const float* zj, int r) {
    return (r < BB) ? (zi + (size_t)r * DD) : (zj + (size_t)(r - BB) * DD);
}

__device__ __forceinline__ void cp16(uint32_t dst_smem, const float* src) {
    asm volatile("cp.async.cg.shared.global [%0], [%1], 16;"
                 :: "r"(dst_smem), "l"(src));
}

__device__ __forceinline__ void ldg4(float4& v, const float* p) {
    asm volatile("ld.global.nc.v4.f32 {%0,%1,%2,%3}, [%4];"
                 : "=f"(v.x), "=f"(v.y), "=f"(v.z), "=f"(v.w)
                 : "l"(p));
}

// One warp per row. NEGATIVES staged via cp.async (structural MLP=16/lane,
// only 32KB smem -> 7 blocks/SM, 28 warps). Own row + positive via ld.nc
// register loads issued BEFORE the cp.async wait (latency hidden under the
// bulk fill). Tail: st.cg partial + red.release ticket; block 0 reduces in
// fixed order (deterministic) and resets the ticket for graph replay.
__global__ void __launch_bounds__(128) fused_kernel(const float* __restrict__ zi,
                                                    const float* __restrict__ zj,
                                                    const int* __restrict__ neg_idx,
                                                    float* __restrict__ out) {
    __shared__ float4 n_buf[4][RR][DD / 4];      // 32 KB: 4 warps x 4 negatives
    __shared__ float  s_nll[4];
    __shared__ float  s_ws[4];

    int warp = threadIdx.x >> 5;
    int lane = threadIdx.x & 31;
    int row  = blockIdx.x * 4 + warp;
    int col  = lane * 4;

    int4 nv = *reinterpret_cast<const int4*>(neg_idx + row * RR);
    int neg[RR];
    neg[0] = nv.x + (nv.x >= row ? 1 : 0);
    neg[1] = nv.y + (nv.y >= row ? 1 : 0);
    neg[2] = nv.z + (nv.z >= row ? 1 : 0);
    neg[3] = nv.w + (nv.w >= row ? 1 : 0);

    // ---- stage 4 negatives: 16 cp.async per lane, one group ----
#pragma unroll
    for (int p = 0; p < RR; p++) {
        const float* gn = row_ptr(zi, zj, neg[p]);
        uint32_t dn = (uint32_t)__cvta_generic_to_shared(&n_buf[warp][p][lane]);
#pragma unroll
        for (int k = 0; k < 4; k++)
            cp16(dn + k * 32 * 16, gn + col + k * 128);
    }
    asm volatile("cp.async.commit_group;");

    // ---- own row + positive partner via nc loads (overlap the fill) ----
    int pos = (row + BB) & (NN - 1);
    const float* px = row_ptr(zi, zj, row);
    const float* pp = row_ptr(zi, zj, pos);
    float4 x[4], z[4];
#pragma unroll
    for (int k = 0; k < 4; k++) ldg4(x[k], px + col + k * 128);
#pragma unroll
    for (int k = 0; k < 4; k++) ldg4(z[k], pp + col + k * 128);

    // Register-side math while negatives land in smem
    float x2 = 0.0f, pdot = 0.0f, z2 = 0.0f;
#pragma unroll
    for (int k = 0; k < 4; k++) {
        float4 a = x[k], b = z[k];
        x2   += a.x * a.x + a.y * a.y + a.z * a.z + a.w * a.w;
        pdot += a.x * b.x + a.y * b.y + a.z * b.z + a.w * b.w;
        z2   += b.x * b.x + b.y * b.y + b.z * b.z + b.w * b.w;
    }

    asm volatile("cp.async.wait_group 0;" ::: "memory");

    // ---- negative dots + norms from smem ----
    float dot[RR], y2[RR];
#pragma unroll
    for (int p = 0; p < RR; p++) {
        float d = 0.0f, n = 0.0f;
#pragma unroll
        for (int k = 0; k < 4; k++) {
            float4 b = n_buf[warp][p][lane + 32 * k];
            float4 a = x[k];
            d += a.x * b.x + a.y * b.y + a.z * b.z + a.w * b.w;
            n += b.x * b.x + b.y * b.y + b.z * b.z + b.w * b.w;
        }
        dot[p] = d;
        y2[p]  = n;
    }

    // ---- warp reductions (11 values) ----
#pragma unroll
    for (int o = 16; o; o >>= 1) {
        x2   += __shfl_xor_sync(0xFFFFFFFFu, x2, o);
        pdot += __shfl_xor_sync(0xFFFFFFFFu, pdot, o);
        z2   += __shfl_xor_sync(0xFFFFFFFFu, z2, o);
#pragma unroll
        for (int p = 0; p < RR; p++) {
            dot[p] += __shfl_xor_sync(0xFFFFFFFFu, dot[p], o);
            y2[p]  += __shfl_xor_sync(0xFFFFFFFFu, y2[p], o);
        }
    }

    if (lane == 0) {
        const float invT = 1.0f / (0.5f + 1e-8f);
        float rnx = 1.0f / fmaxf(sqrtf(x2), 1e-8f);
        float l[5];
        {
            float rnz = 1.0f / fmaxf(sqrtf(z2), 1e-8f);
            l[0] = pdot * rnx * rnz * invT;
        }
#pragma unroll
        for (int p = 0; p < RR; p++) {
            float rny = 1.0f / fmaxf(sqrtf(y2[p]), 1e-8f);
            l[p + 1] = dot[p] * rnx * rny * invT;
        }
        float m = l[0];
#pragma unroll
        for (int p = 1; p < 5; p++) m = fmaxf(m, l[p]);
        float se = 0.0f;
#pragma unroll
        for (int p = 0; p < 5; p++) se += expf(l[p] - m);
        s_nll[warp] = m + logf(se) - l[0];
    }
    __syncthreads();

    // ---- free tail: partial to L2 + fire-and-forget release ticket ----
    if (threadIdx.x == 0) {
        float partial = s_nll[0] + s_nll[1] + s_nll[2] + s_nll[3];
        asm volatile("st.global.cg.f32 [%0], %1;"
                     :: "l"(&g_partial[blockIdx.x]), "f"(partial) : "memory");
        asm volatile("red.release.gpu.global.add.u32 [%0], 1;"
                     :: "l"(&g_ticket) : "memory");
    }

    // ---- block 0 = designated reducer (deterministic, fixed order) ----
    if (blockIdx.x == 0) {
        if (threadIdx.x == 0) {
            unsigned int v;
            do {
                __nanosleep(64);
                asm volatile("ld.acquire.gpu.global.u32 %0, [%1];"
                             : "=r"(v) : "l"(&g_ticket));
            } while (v < (unsigned int)NBLK);
        }
        __syncthreads();

        float s = 0.0f;
#pragma unroll
        for (int k = 0; k < NBLK / 128; k++) {
            float v;
            asm volatile("ld.global.cg.f32 %0, [%1];"
                         : "=f"(v) : "l"(&g_partial[threadIdx.x + k * 128]));
            s += v;
        }
#pragma unroll
        for (int o = 16; o; o >>= 1) s += __shfl_xor_sync(0xFFFFFFFFu, s, o);
        if (lane == 0) s_ws[warp] = s;
        __syncthreads();
        if (threadIdx.x == 0) {
            float tot = s_ws[0] + s_ws[1] + s_ws[2] + s_ws[3];
            out[0] = tot * (1.0f / (float)NN);
            g_ticket = 0u;   // all blocks arrived; safe reset for next replay
        }
    }
}

extern "C" void kernel_launch(void* const* d_in, const int* in_sizes, int n_in,
                              void* d_out, int out_size) {
    const float* zi      = (const float*)d_in[0];
    const float* zj      = (const float*)d_in[1];
    const int*   neg_idx = (const int*)d_in[2];
    float* out = (float*)d_out;

    fused_kernel<<<NBLK, 128>>>(zi, zj, neg_idx, out);
}